// round 8
// baseline (speedup 1.0000x reference)
#include <cuda_runtime.h>
#include <cstdint>
#include <math.h>

#define DIM      128
#define NPARAMS  8384
#define NT       256            // 8 warps

// Two-region triangular L layout (floats), plain row-major columns:
//  region A: rows 0-63, 64 cols, stride 68
//  region B: rows 64-127, 128 cols, stride 132
#define RS_A     68
#define RS_B     132
#define OFF_A    0
#define OFF_B    (64 * RS_A)            // 4352
#define OFF_EPS  (OFF_B + 64 * RS_B)    // 12800
#define OFF_LD   (OFF_EPS + 128)
#define OFF_MEAN (OFF_LD + 128)
#define OFF_DIAG (OFF_MEAN + 128)
#define SMEM_FLOATS (OFF_DIAG + 128)    // 13312 floats = 53248 B

// Per-warp m16n16 lower-triangle tile lists, (mt<<4)|nt, 0xFF = end.
// MMA cost per tile = 4*(nt+1); each warp sums to 60 MMAs.
__constant__ uint8_t TILE_TAB[8][8] = {
    {0x77, 0x43, 0x11, 0x00, 0xFF, 0xFF, 0xFF, 0xFF},
    {0x66, 0x54, 0x21, 0x30, 0xFF, 0xFF, 0xFF, 0xFF},
    {0x76, 0x44, 0x22, 0xFF, 0xFF, 0xFF, 0xFF, 0xFF},
    {0x55, 0x65, 0x32, 0xFF, 0xFF, 0xFF, 0xFF, 0xFF},
    {0x75, 0x64, 0x33, 0xFF, 0xFF, 0xFF, 0xFF, 0xFF},
    {0x74, 0x53, 0x31, 0x41, 0x20, 0x40, 0xFF, 0xFF},
    {0x63, 0x73, 0x42, 0x52, 0x10, 0xFF, 0xFF, 0xFF},
    {0x62, 0x72, 0x51, 0x61, 0x71, 0x50, 0x60, 0x70},
};

__device__ __forceinline__ int rowbase(int r) {
    return (r < 64) ? (OFF_A + r * RS_A) : (OFF_B + (r - 64) * RS_B);
}

__device__ __forceinline__ void mma_tf32(float* d, uint32_t a0, uint32_t a1,
                                         uint32_t a2, uint32_t a3,
                                         uint32_t b0, uint32_t b1) {
    asm volatile(
        "mma.sync.aligned.m16n8k8.row.col.f32.tf32.tf32.f32 "
        "{%0,%1,%2,%3}, {%4,%5,%6,%7}, {%8,%9}, {%0,%1,%2,%3};"
        : "+f"(d[0]), "+f"(d[1]), "+f"(d[2]), "+f"(d[3])
        : "r"(a0), "r"(a1), "r"(a2), "r"(a3), "r"(b0), "r"(b1));
}

__device__ __forceinline__ uint32_t to_tf32(float v) {
    uint32_t t;
    asm("cvt.rna.tf32.f32 %0, %1;" : "=r"(t) : "f"(v));
    return t;
}

// Transform one float4 chunk of row r (cols j0..j0+3) and store (tf32) to smem.
__device__ __forceinline__ void xform_store(float* smf, const int rbase,
                                            const int r, const int j0,
                                            const float rw, float4 v,
                                            bool has_data) {
    if (!has_data) {
        v = make_float4(0.f, 0.f, 0.f, 0.f);
    } else if (j0 + 3 < r) {
        v.x *= rw; v.y *= rw; v.z *= rw; v.w *= rw;
    } else {
        float vv[4] = {v.x, v.y, v.z, v.w};
        #pragma unroll
        for (int e = 0; e < 4; e++) {
            int j = j0 + e;
            float raw = vv[e];
            if (j < r)       vv[e] = raw * rw;
            else if (j == r) { smf[OFF_LD + r] = raw; vv[e] = expf(raw); }
            else             vv[e] = 0.0f;
        }
        v = make_float4(vv[0], vv[1], vv[2], vv[3]);
    }
    *(uint4*)&smf[rbase + j0] =
        make_uint4(to_tf32(v.x), to_tf32(v.y), to_tf32(v.z), to_tf32(v.w));
}

__global__ __launch_bounds__(NT, 4)
void fld_mma_kernel(const float* __restrict__ params,
                    const float* __restrict__ eps,
                    float* __restrict__ sample,
                    float* __restrict__ kl,
                    float* __restrict__ sigma)
{
    extern __shared__ float smf[];

    const int b   = blockIdx.x;
    const int tid = threadIdx.x;
    const int wid = tid >> 5;
    const int lid = tid & 31;
    const int gr  = lid >> 2;       // octet row 0..7
    const int tg  = lid & 3;        // thread-in-quad 0..3
    const float* P = params + (size_t)b * NPARAMS;

    // ---- phase 0: mean, eps ----
    if (tid < DIM) {
        smf[OFF_MEAN + tid] = P[tid];
        smf[OFF_EPS + tid]  = eps[(size_t)b * DIM + tid];
    }

    // ---- phase 1: coalesced triangular unpack ----
    // Row sources are contiguous in params:
    //   r < 64 : P[256 + 128r + j], ascending
    //   r >= 64: P[16511 - 128r - j], descending (float4 + register reverse)
    #pragma unroll
    for (int q = 0; q < 8; q++) {
        const int r  = 64 + wid + 8 * q;
        const int j0 = lid << 2;
        const int cb = (r & ~15) + 16;          // exclusive col bound
        if (j0 < cb) {
            const float rw = rsqrtf((float)(r + 1));
            float4 v = make_float4(0.f, 0.f, 0.f, 0.f);
            const bool has = (j0 <= r);
            if (has) {
                float4 w4 = *(const float4*)(P + 16508 - 128 * r - j0);
                v = make_float4(w4.w, w4.z, w4.y, w4.x);
            }
            xform_store(smf, OFF_B + (r - 64) * RS_B, r, j0, rw, v, has);
        }
    }
    #pragma unroll
    for (int q = 0; q < 4; q++) {
        const int hw = lid >> 4;
        const int hl = lid & 15;
        const int rA = wid + 8 * q;
        const int r  = hw ? (63 - rA) : rA;
        const int j0 = hl << 2;
        const int cb = (r & ~15) + 16;
        if (j0 < cb) {
            const float rw = rsqrtf((float)(r + 1));
            float4 v = make_float4(0.f, 0.f, 0.f, 0.f);
            const bool has = (j0 <= r);
            if (has)
                v = *(const float4*)(P + 256 + 128 * r + j0);
            xform_store(smf, OFF_A + r * RS_A, r, j0, rw, v, has);
        }
    }
    __syncthreads();

    // ---- phase 2a: lower-triangle m16n16 tiles, coalesced STG.128 ----
    float* Sg = sigma + (size_t)b * DIM * DIM;

    for (int t = 0; t < 8; t++) {
        const uint32_t code = TILE_TAB[wid][t];
        if (code == 0xFF) break;
        const int mt = code >> 4, nt = code & 15;
        const int m0 = mt * 16, n0 = nt * 16;
        const int rs_m = (mt < 4) ? RS_A : RS_B;
        const int rs_n = (nt < 4) ? RS_A : RS_B;
        const int ar0 = rowbase(m0 + gr) + tg;
        const int ar1 = ar0 + 8 * rs_m;
        const int br0 = rowbase(n0 + gr) + tg;
        const int br1 = br0 + 8 * rs_n;
        const int ksteps = 2 * (nt + 1);

        float d[2][4];
        #pragma unroll
        for (int s = 0; s < 2; s++)
            #pragma unroll
            for (int c = 0; c < 4; c++) d[s][c] = 0.0f;

        if (mt == nt) {
            // diagonal tile: B fragments alias A fragments
            #pragma unroll 2
            for (int ks = 0; ks < ksteps; ks++) {
                const int k0 = ks * 8;
                uint32_t a0 = *(const uint32_t*)&smf[ar0 + k0];
                uint32_t a2 = *(const uint32_t*)&smf[ar0 + k0 + 4];
                uint32_t a1 = *(const uint32_t*)&smf[ar1 + k0];
                uint32_t a3 = *(const uint32_t*)&smf[ar1 + k0 + 4];
                mma_tf32(d[0], a0, a1, a2, a3, a0, a2);
                mma_tf32(d[1], a0, a1, a2, a3, a1, a3);
            }
        } else {
            #pragma unroll 2
            for (int ks = 0; ks < ksteps; ks++) {
                const int k0 = ks * 8;
                uint32_t a0 = *(const uint32_t*)&smf[ar0 + k0];
                uint32_t a2 = *(const uint32_t*)&smf[ar0 + k0 + 4];
                uint32_t a1 = *(const uint32_t*)&smf[ar1 + k0];
                uint32_t a3 = *(const uint32_t*)&smf[ar1 + k0 + 4];
                uint32_t b0x = *(const uint32_t*)&smf[br0 + k0];
                uint32_t b0y = *(const uint32_t*)&smf[br0 + k0 + 4];
                uint32_t b1x = *(const uint32_t*)&smf[br1 + k0];
                uint32_t b1y = *(const uint32_t*)&smf[br1 + k0 + 4];
                mma_tf32(d[0], a0, a1, a2, a3, b0x, b0y);
                mma_tf32(d[1], a0, a1, a2, a3, b1x, b1y);
            }
        }

        // diagonal extraction (before any repacking)
        if (mt == nt && 2 * tg == (gr & ~1)) {
            int c = gr & 1;
            smf[OFF_DIAG + m0 + gr]     = d[0][c];
            smf[OFF_DIAG + m0 + gr + 8] = d[1][2 + c];
        }

        // ---- direct store: repack to float4 (cols 4q..4q+3), 2x STG.128 ----
        {
            const int coff = (tg & 1) ? (6 + 2 * tg) : (2 * tg);
            float e0 = __shfl_xor_sync(0xffffffffu, d[0][0], 1);
            float e1 = __shfl_xor_sync(0xffffffffu, d[0][1], 1);
            float o0 = __shfl_xor_sync(0xffffffffu, d[1][0], 1);
            float o1 = __shfl_xor_sync(0xffffffffu, d[1][1], 1);
            float4 v0 = (tg & 1) ? make_float4(o0, o1, d[1][0], d[1][1])
                                 : make_float4(d[0][0], d[0][1], e0, e1);
            *(float4*)&Sg[(size_t)(m0 + gr) * DIM + n0 + coff] = v0;

            e0 = __shfl_xor_sync(0xffffffffu, d[0][2], 1);
            e1 = __shfl_xor_sync(0xffffffffu, d[0][3], 1);
            o0 = __shfl_xor_sync(0xffffffffu, d[1][2], 1);
            o1 = __shfl_xor_sync(0xffffffffu, d[1][3], 1);
            float4 v1 = (tg & 1) ? make_float4(o0, o1, d[1][2], d[1][3])
                                 : make_float4(d[0][2], d[0][3], e0, e1);
            *(float4*)&Sg[(size_t)(m0 + gr + 8) * DIM + n0 + coff] = v1;
        }

        if (mt != nt) {
            // ---- mirror store: xor4 transpose stage, then xor8 merge ----
            const int odd   = gr & 1;
            const int coffm = ((gr >> 2) & 1) * 4 + ((gr >> 1) & 1) * 8;
            const bool hi   = (gr & 2) != 0;
            #pragma unroll
            for (int s = 0; s < 2; s++) {
                float q0 = __shfl_xor_sync(0xffffffffu, d[s][0], 4);
                float q1 = __shfl_xor_sync(0xffffffffu, d[s][1], 4);
                float q2 = __shfl_xor_sync(0xffffffffu, d[s][2], 4);
                float q3 = __shfl_xor_sync(0xffffffffu, d[s][3], 4);
                // w0: cols m0+(gr&~1)+{0,1}; w1: cols +8; row n0+8s+2tg+odd
                float2 w0 = odd ? make_float2(q1, d[s][1]) : make_float2(d[s][0], q0);
                float2 w1 = odd ? make_float2(q3, d[s][3]) : make_float2(d[s][2], q2);
                float r0x = __shfl_xor_sync(0xffffffffu, w0.x, 8);
                float r0y = __shfl_xor_sync(0xffffffffu, w0.y, 8);
                float r1x = __shfl_xor_sync(0xffffffffu, w1.x, 8);
                float r1y = __shfl_xor_sync(0xffffffffu, w1.y, 8);
                float4 vm = hi ? make_float4(r1x, r1y, w1.x, w1.y)
                               : make_float4(w0.x, w0.y, r0x, r0y);
                int rowt = n0 + 8 * s + 2 * tg + odd;
                *(float4*)&Sg[(size_t)rowt * DIM + m0 + coffm] = vm;
            }
        }
    }

    // ---- phase 2b: sample = mean + L*eps (2 threads per row) ----
    {
        const int u = tid >> 1, h = tid & 1;
        const int r = (u & 1) ? (127 - (u >> 1)) : (u >> 1);
        const int c4tot = (r >> 2) + 1;
        const int ch0   = (c4tot + 1) >> 1;
        const int cbeg  = h ? ch0 : 0;
        const int cend  = h ? c4tot : ch0;
        const int rbase = rowbase(r);
        float dot = 0.0f;
        for (int c = cbeg; c < cend; c++) {
            const int j0 = c << 2;
            float4 lv = *(const float4*)&smf[rbase + j0];
            float4 ev = *(const float4*)&smf[OFF_EPS + j0];
            dot = fmaf(lv.x, ev.x, dot);
            dot = fmaf(lv.y, ev.y, dot);
            dot = fmaf(lv.z, ev.z, dot);
            dot = fmaf(lv.w, ev.w, dot);
        }
        dot += __shfl_xor_sync(0xffffffffu, dot, 1);
        if (!h)
            sample[(size_t)b * DIM + r] = smf[OFF_MEAN + r] + dot;
    }
    __syncthreads();   // s_diag / s_ld complete

    // ---- phase 3: kl (warp 0) ----
    if (wid == 0) {
        float t = 0.0f;
        #pragma unroll
        for (int k = 0; k < 4; k++) {
            int rr = lid + 32 * k;
            float m = smf[OFF_MEAN + rr];
            t += smf[OFF_DIAG + rr] - 1.0f + m * m - 2.0f * smf[OFF_LD + rr];
        }
        #pragma unroll
        for (int o = 16; o > 0; o >>= 1)
            t += __shfl_down_sync(0xffffffffu, t, o);
        if (lid == 0) kl[b] = 0.5f * t;
    }
}

extern "C" void kernel_launch(void* const* d_in, const int* in_sizes, int n_in,
                              void* d_out, int out_size)
{
    const float* params = (const float*)d_in[0];
    const float* eps    = (const float*)d_in[1];
    const int B = in_sizes[0] / NPARAMS;

    float* out    = (float*)d_out;
    float* sample = out;                       // B * 128
    float* kl     = out + (size_t)B * DIM;     // B
    float* sigma  = kl + B;                    // B * 128 * 128

    const int smem = SMEM_FLOATS * sizeof(float);
    cudaFuncSetAttribute(fld_mma_kernel,
                         cudaFuncAttributeMaxDynamicSharedMemorySize, smem);
    fld_mma_kernel<<<B, NT, smem>>>(params, eps, sample, kl, sigma);
}

// round 9
// speedup vs baseline: 1.0880x; 1.0880x over previous
#include <cuda_runtime.h>
#include <cstdint>
#include <math.h>

#define DIM      128
#define NPARAMS  8384
#define NT       256            // 8 warps

// Two-region triangular L layout (floats), plain row-major columns:
//  region A: rows 0-63, 64 cols, stride 68
//  region B: rows 64-127, 128 cols, stride 132
#define RS_A     68
#define RS_B     132
#define OFF_A    0
#define OFF_B    (64 * RS_A)            // 4352
#define OFF_EPS  (OFF_B + 64 * RS_B)    // 12800
#define OFF_LD   (OFF_EPS + 128)
#define OFF_MEAN (OFF_LD + 128)
#define OFF_DIAG (OFF_MEAN + 128)
#define SMEM_FLOATS (OFF_DIAG + 128)    // 13312 floats = 53248 B

// Work items: bit6 = pair (tiles (mt,nt) and (mt+1,nt)), bits5:3 = mt,
// bits2:0 = nt. 0xFF = end. Per-warp MMA cost 56-64; all 36 tiles covered.
__constant__ uint8_t TILE_TAB[8][6] = {
    {0x76, 0x40, 0xFF, 0xFF, 0xFF, 0xFF},  // (6,7|6)p (0,1|0)p      = 64
    {0x6D, 0x49, 0xFF, 0xFF, 0xFF, 0xFF},  // (5,6|5)p (1,2|1)p      = 64
    {0x64, 0x52, 0xFF, 0xFF, 0xFF, 0xFF},  // (4,5|4)p (2,3|2)p      = 64
    {0x74, 0x62, 0xFF, 0xFF, 0xFF, 0xFF},  // (6,7|4)p (4,5|2)p      = 64
    {0x5B, 0x3D, 0xFF, 0xFF, 0xFF, 0xFF},  // (3,4|3)p (7|5)s        = 56
    {0x6B, 0x72, 0xFF, 0xFF, 0xFF, 0xFF},  // (5,6|3)p (6,7|2)p      = 56
    {0x3F, 0x3B, 0x50, 0xFF, 0xFF, 0xFF},  // (7|7)s (7|3)s (2,3|0)p = 56
    {0x59, 0x69, 0x39, 0x60, 0x70, 0xFF},  // (3,4|1)p (5,6|1)p (7|1)s (4,5|0)p (6,7|0)p = 56
};

__device__ __forceinline__ int rowbase(int r) {
    return (r < 64) ? (OFF_A + r * RS_A) : (OFF_B + (r - 64) * RS_B);
}

__device__ __forceinline__ void mma_tf32(float* d, uint32_t a0, uint32_t a1,
                                         uint32_t a2, uint32_t a3,
                                         uint32_t b0, uint32_t b1) {
    asm volatile(
        "mma.sync.aligned.m16n8k8.row.col.f32.tf32.tf32.f32 "
        "{%0,%1,%2,%3}, {%4,%5,%6,%7}, {%8,%9}, {%0,%1,%2,%3};"
        : "+f"(d[0]), "+f"(d[1]), "+f"(d[2]), "+f"(d[3])
        : "r"(a0), "r"(a1), "r"(a2), "r"(a3), "r"(b0), "r"(b1));
}

__device__ __forceinline__ uint32_t to_tf32(float v) {
    uint32_t t;
    asm("cvt.rna.tf32.f32 %0, %1;" : "=r"(t) : "f"(v));
    return t;
}

// Transform one float4 chunk of row r (cols j0..j0+3) and store (tf32) to smem.
__device__ __forceinline__ void xform_store(float* smf, const int rbase,
                                            const int r, const int j0,
                                            const float rw, float4 v,
                                            bool has_data) {
    if (!has_data) {
        v = make_float4(0.f, 0.f, 0.f, 0.f);
    } else if (j0 + 3 < r) {
        v.x *= rw; v.y *= rw; v.z *= rw; v.w *= rw;
    } else {
        float vv[4] = {v.x, v.y, v.z, v.w};
        #pragma unroll
        for (int e = 0; e < 4; e++) {
            int j = j0 + e;
            float raw = vv[e];
            if (j < r)       vv[e] = raw * rw;
            else if (j == r) { smf[OFF_LD + r] = raw; vv[e] = expf(raw); }
            else             vv[e] = 0.0f;
        }
        v = make_float4(vv[0], vv[1], vv[2], vv[3]);
    }
    *(uint4*)&smf[rbase + j0] =
        make_uint4(to_tf32(v.x), to_tf32(v.y), to_tf32(v.z), to_tf32(v.w));
}

// R7 store scheme: direct float2 stores; mirror via xor4 shuffles; diag extract.
__device__ __forceinline__ void store_tile(float* Sg, float* smf,
                                           const float d[2][4],
                                           int m0, int n0, int gr, int tg,
                                           bool diag) {
    #pragma unroll
    for (int s = 0; s < 2; s++) {
        int col = n0 + 8 * s + 2 * tg;
        *(float2*)&Sg[(size_t)(m0 + gr) * DIM + col]     = make_float2(d[s][0], d[s][1]);
        *(float2*)&Sg[(size_t)(m0 + gr + 8) * DIM + col] = make_float2(d[s][2], d[s][3]);
    }
    if (!diag) {
        const int odd  = gr & 1;
        const int colt = m0 + (gr & ~1);
        #pragma unroll
        for (int s = 0; s < 2; s++) {
            float q0 = __shfl_xor_sync(0xffffffffu, d[s][0], 4);
            float q1 = __shfl_xor_sync(0xffffffffu, d[s][1], 4);
            float q2 = __shfl_xor_sync(0xffffffffu, d[s][2], 4);
            float q3 = __shfl_xor_sync(0xffffffffu, d[s][3], 4);
            int rowt = n0 + 8 * s + 2 * tg + odd;
            float2 w0 = odd ? make_float2(q1, d[s][1]) : make_float2(d[s][0], q0);
            float2 w1 = odd ? make_float2(q3, d[s][3]) : make_float2(d[s][2], q2);
            *(float2*)&Sg[(size_t)rowt * DIM + colt]     = w0;
            *(float2*)&Sg[(size_t)rowt * DIM + colt + 8] = w1;
        }
    } else if (2 * tg == (gr & ~1)) {
        int c = gr & 1;
        smf[OFF_DIAG + m0 + gr]     = d[0][c];
        smf[OFF_DIAG + m0 + gr + 8] = d[1][2 + c];
    }
}

__global__ __launch_bounds__(NT, 4)
void fld_mma_kernel(const float* __restrict__ params,
                    const float* __restrict__ eps,
                    float* __restrict__ sample,
                    float* __restrict__ kl,
                    float* __restrict__ sigma)
{
    extern __shared__ float smf[];

    const int b   = blockIdx.x;
    const int tid = threadIdx.x;
    const int wid = tid >> 5;
    const int lid = tid & 31;
    const int gr  = lid >> 2;       // octet row 0..7
    const int tg  = lid & 3;        // thread-in-quad 0..3
    const float* P = params + (size_t)b * NPARAMS;

    // ---- phase 0: mean, eps ----
    if (tid < DIM) {
        smf[OFF_MEAN + tid] = P[tid];
        smf[OFF_EPS + tid]  = eps[(size_t)b * DIM + tid];
    }

    // ---- phase 1: coalesced triangular unpack ----
    //   r < 64 : P[256 + 128r + j], ascending
    //   r >= 64: P[16511 - 128r - j], descending (float4 + register reverse)
    #pragma unroll
    for (int q = 0; q < 8; q++) {
        const int r  = 64 + wid + 8 * q;
        const int j0 = lid << 2;
        const int cb = (r & ~15) + 16;          // exclusive col bound
        if (j0 < cb) {
            const float rw = rsqrtf((float)(r + 1));
            float4 v = make_float4(0.f, 0.f, 0.f, 0.f);
            const bool has = (j0 <= r);
            if (has) {
                float4 w4 = *(const float4*)(P + 16508 - 128 * r - j0);
                v = make_float4(w4.w, w4.z, w4.y, w4.x);
            }
            xform_store(smf, OFF_B + (r - 64) * RS_B, r, j0, rw, v, has);
        }
    }
    #pragma unroll
    for (int q = 0; q < 4; q++) {
        const int hw = lid >> 4;
        const int hl = lid & 15;
        const int rA = wid + 8 * q;
        const int r  = hw ? (63 - rA) : rA;
        const int j0 = hl << 2;
        const int cb = (r & ~15) + 16;
        if (j0 < cb) {
            const float rw = rsqrtf((float)(r + 1));
            float4 v = make_float4(0.f, 0.f, 0.f, 0.f);
            const bool has = (j0 <= r);
            if (has)
                v = *(const float4*)(P + 256 + 128 * r + j0);
            xform_store(smf, OFF_A + r * RS_A, r, j0, rw, v, has);
        }
    }
    __syncthreads();

    // ---- phase 2a: m32n16 paired / single tiles ----
    float* Sg = sigma + (size_t)b * DIM * DIM;

    for (int t = 0; t < 6; t++) {
        const uint32_t code = TILE_TAB[wid][t];
        if (code == 0xFF) break;
        const bool pair = (code & 0x40) != 0;
        const int mt0 = (code >> 3) & 7;
        const int nt  = code & 7;
        const int n0  = nt * 16;
        const int m0a = mt0 * 16;
        const int ksteps = 2 * (nt + 1);
        const bool alias = (mt0 == nt);     // B rows == sub0 A rows

        const int rs_a = (mt0 < 4) ? RS_A : RS_B;
        const int ar0 = rowbase(m0a + gr) + tg;
        const int ar1 = ar0 + 8 * rs_a;
        const int rs_c = (mt0 + 1 < 4) ? RS_A : RS_B;
        const int cr0 = rowbase(((mt0 + 1) & 7) * 16 + gr) + tg;
        const int cr1 = cr0 + 8 * rs_c;
        const int rs_b = (nt < 4) ? RS_A : RS_B;
        const int br0 = rowbase(n0 + gr) + tg;
        const int br1 = br0 + 8 * rs_b;

        float d0[2][4], d1[2][4];
        #pragma unroll
        for (int s = 0; s < 2; s++)
            #pragma unroll
            for (int c = 0; c < 4; c++) { d0[s][c] = 0.0f; d1[s][c] = 0.0f; }

        #pragma unroll 2
        for (int ks = 0; ks < ksteps; ks++) {
            const int k0 = ks * 8;
            uint32_t a0 = *(const uint32_t*)&smf[ar0 + k0];
            uint32_t a2 = *(const uint32_t*)&smf[ar0 + k0 + 4];
            uint32_t a1 = *(const uint32_t*)&smf[ar1 + k0];
            uint32_t a3 = *(const uint32_t*)&smf[ar1 + k0 + 4];
            uint32_t b0x, b0y, b1x, b1y;
            if (alias) {
                b0x = a0; b0y = a2; b1x = a1; b1y = a3;
            } else {
                b0x = *(const uint32_t*)&smf[br0 + k0];
                b0y = *(const uint32_t*)&smf[br0 + k0 + 4];
                b1x = *(const uint32_t*)&smf[br1 + k0];
                b1y = *(const uint32_t*)&smf[br1 + k0 + 4];
            }
            mma_tf32(d0[0], a0, a1, a2, a3, b0x, b0y);
            mma_tf32(d0[1], a0, a1, a2, a3, b1x, b1y);
            if (pair) {
                uint32_t c0 = *(const uint32_t*)&smf[cr0 + k0];
                uint32_t c2 = *(const uint32_t*)&smf[cr0 + k0 + 4];
                uint32_t c1 = *(const uint32_t*)&smf[cr1 + k0];
                uint32_t c3 = *(const uint32_t*)&smf[cr1 + k0 + 4];
                mma_tf32(d1[0], c0, c1, c2, c3, b0x, b0y);
                mma_tf32(d1[1], c0, c1, c2, c3, b1x, b1y);
            }
        }

        store_tile(Sg, smf, d0, m0a, n0, gr, tg, alias);
        if (pair)
            store_tile(Sg, smf, d1, m0a + 16, n0, gr, tg, false);
    }

    // ---- phase 2b: sample = mean + L*eps (2 threads per row) ----
    {
        const int u = tid >> 1, h = tid & 1;
        const int r = (u & 1) ? (127 - (u >> 1)) : (u >> 1);
        const int c4tot = (r >> 2) + 1;
        const int ch0   = (c4tot + 1) >> 1;
        const int cbeg  = h ? ch0 : 0;
        const int cend  = h ? c4tot : ch0;
        const int rbase = rowbase(r);
        float dot = 0.0f;
        for (int c = cbeg; c < cend; c++) {
            const int j0 = c << 2;
            float4 lv = *(const float4*)&smf[rbase + j0];
            float4 ev = *(const float4*)&smf[OFF_EPS + j0];
            dot = fmaf(lv.x, ev.x, dot);
            dot = fmaf(lv.y, ev.y, dot);
            dot = fmaf(lv.z, ev.z, dot);
            dot = fmaf(lv.w, ev.w, dot);
        }
        dot += __shfl_xor_sync(0xffffffffu, dot, 1);
        if (!h)
            sample[(size_t)b * DIM + r] = smf[OFF_MEAN + r] + dot;
    }
    __syncthreads();   // s_diag / s_ld complete

    // ---- phase 3: kl (warp 0) ----
    if (wid == 0) {
        float t = 0.0f;
        #pragma unroll
        for (int k = 0; k < 4; k++) {
            int rr = lid + 32 * k;
            float m = smf[OFF_MEAN + rr];
            t += smf[OFF_DIAG + rr] - 1.0f + m * m - 2.0f * smf[OFF_LD + rr];
        }
        #pragma unroll
        for (int o = 16; o > 0; o >>= 1)
            t += __shfl_down_sync(0xffffffffu, t, o);
        if (lid == 0) kl[b] = 0.5f * t;
    }
}

extern "C" void kernel_launch(void* const* d_in, const int* in_sizes, int n_in,
                              void* d_out, int out_size)
{
    const float* params = (const float*)d_in[0];
    const float* eps    = (const float*)d_in[1];
    const int B = in_sizes[0] / NPARAMS;

    float* out    = (float*)d_out;
    float* sample = out;                       // B * 128
    float* kl     = out + (size_t)B * DIM;     // B
    float* sigma  = kl + B;                    // B * 128 * 128

    const int smem = SMEM_FLOATS * sizeof(float);
    cudaFuncSetAttribute(fld_mma_kernel,
                         cudaFuncAttributeMaxDynamicSharedMemorySize, smem);
    fld_mma_kernel<<<B, NT, smem>>>(params, eps, sample, kl, sigma);
}